// round 4
// baseline (speedup 1.0000x reference)
#include <cuda_runtime.h>
#include <math.h>

// Problem constants (fixed: point_cloud [8, 4096, 3], K=20)
#define BATCH 8
#define NPTS  4096
#define KNN   20
#define KS    25            // approx top-25: true top-21 (self+20) guaranteed inside
#define KE    21            // exact list: self + 20 neighbors
#define TPB   128
#define CHUNKS (NPTS / TPB) // 32
#define NSPLIT 2
#define HALF  (NPTS / NSPLIT)   // 2048 candidates per partial CTA

// Partial top-KS packed keys per (query, half): 8*4096*2*25*4B = 6.55 MB (L2-resident)
__device__ unsigned g_keys[BATCH * NPTS * NSPLIT * KS];

// ---------------------------------------------------------------------------
// Kernel 1: partial KNN over one half of the candidate set.
// key = round_to_nearest_12bit(d2 float bits) | candidate_index (12 bits)
// ---------------------------------------------------------------------------
__global__ __launch_bounds__(TPB)
void knn_partial_kernel(const float* __restrict__ pc)
{
    extern __shared__ float4 pts[];        // HALF * 16B = 32 KB

    const int cta   = blockIdx.x;                  // [0, 512)
    const int half  = cta & (NSPLIT - 1);
    const int chunk = (cta / NSPLIT) % CHUNKS;
    const int b     = cta / (NSPLIT * CHUNKS);
    const float* __restrict__ pcb = pc + (size_t)b * NPTS * 3;
    const int cbase = half * HALF;

    for (int i = threadIdx.x; i < HALF; i += TPB) {
        int gi = cbase + i;
        float x = pcb[3 * gi + 0];
        float y = pcb[3 * gi + 1];
        float z = pcb[3 * gi + 2];
        pts[i] = make_float4(x, y, z, fmaf(x, x, fmaf(y, y, z * z)));
    }
    __syncthreads();

    const int qi = chunk * TPB + threadIdx.x;      // query index in batch
    const float qx = pcb[3 * qi + 0];
    const float qy = pcb[3 * qi + 1];
    const float qz = pcb[3 * qi + 2];
    const float n2qx = -2.0f * qx, n2qy = -2.0f * qy, n2qz = -2.0f * qz;
    const float sqq = fmaf(qx, qx, fmaf(qy, qy, qz * qz));

    unsigned key[KS];
#pragma unroll
    for (int k = 0; k < KS; k++) key[k] = 0xFFFFFFFFu;

#pragma unroll 8
    for (int j = 0; j < HALF; j++) {
        float4 p = pts[j];                         // LDS.128 warp-broadcast
        float t  = fmaf(n2qz, p.z, p.w);
        t        = fmaf(n2qy, p.y, t);
        t        = fmaf(n2qx, p.x, t);
        float d2 = fmaxf(t + sqq, 0.0f);
        unsigned kb = (((__float_as_uint(d2) + 0x800u) & 0xFFFFF000u)
                       | (unsigned)(cbase + j));

        if (kb < key[KS - 1]) {
            unsigned c = kb;
            if (c >= key[KS / 2]) {                // tail-only bubble (common)
#pragma unroll
                for (int k = KS / 2 + 1; k < KS; k++) {
                    unsigned tt = key[k];
                    key[k] = min(c, tt);
                    c      = max(c, tt);
                }
            } else {
#pragma unroll
                for (int k = 0; k < KS; k++) {
                    unsigned tt = key[k];
                    key[k] = min(c, tt);
                    c      = max(c, tt);
                }
            }
        }
    }

    unsigned* __restrict__ dst =
        g_keys + (size_t)((b * NPTS + qi) * NSPLIT + half) * KS;
#pragma unroll
    for (int k = 0; k < KS; k++) dst[k] = key[k];
}

// ---------------------------------------------------------------------------
// Kernel 2: merge the 2 partial lists, exact re-rank, emit outputs.
// ---------------------------------------------------------------------------
__global__ __launch_bounds__(TPB)
void knn_merge_kernel(const float* __restrict__ pc, float* __restrict__ out)
{
    const int row = blockIdx.x * TPB + threadIdx.x;    // [0, BATCH*NPTS)
    const int b   = row / NPTS;
    const int qi  = row - b * NPTS;
    const float* __restrict__ pcb = pc + (size_t)b * NPTS * 3;

    const float qx = pcb[3 * qi + 0];
    const float qy = pcb[3 * qi + 1];
    const float qz = pcb[3 * qi + 2];

    // Merge 2*KS packed keys -> approx top-KS of the union.
    unsigned key[KS];
#pragma unroll
    for (int k = 0; k < KS; k++) key[k] = 0xFFFFFFFFu;

    const unsigned* __restrict__ srck = g_keys + (size_t)row * NSPLIT * KS;
#pragma unroll
    for (int s = 0; s < NSPLIT * KS; s++) {
        unsigned c = srck[s];
        if (c < key[KS - 1]) {
#pragma unroll
            for (int k = 0; k < KS; k++) {
                unsigned tt = key[k];
                key[k] = min(c, tt);
                c      = max(c, tt);
            }
        }
    }

    // Exact fixup: recompute full-precision d2 for the KS survivors and
    // bubble-insert (strict <) into an exact 21-slot list. Stream order is
    // ascending approx key, so exact ties keep index-ascending (top_k-stable).
    float fd[KE];
    int   fi[KE];
#pragma unroll
    for (int k = 0; k < KE; k++) { fd[k] = 3.0e38f; fi[k] = 0; }

#pragma unroll
    for (int s = 0; s < KS; s++) {
        int id = (int)(key[s] & 0xFFFu);
        float dx = pcb[3 * id + 0] - qx;
        float dy = pcb[3 * id + 1] - qy;
        float dz = pcb[3 * id + 2] - qz;
        float d2 = fmaf(dx, dx, fmaf(dy, dy, dz * dz));
        if (d2 < fd[KE - 1]) {
            float c = d2; int ci = id;
#pragma unroll
            for (int k = 0; k < KE; k++) {
                bool  pb = c < fd[k];
                float tv = fd[k]; int ti = fi[k];
                fd[k] = pb ? c  : fd[k];
                fi[k] = pb ? ci : fi[k];
                c     = pb ? tv : c;
                ci    = pb ? ti : ci;
            }
        }
    }
    // Slot 0 is self (exact d2 == 0, strict minimum); neighbors = slots 1..20.

    const long long BNK = (long long)BATCH * NPTS * KNN;
    float dk     = sqrtf(fd[KE - 1]);
    float sigma  = dk + 1e-6f;                 // BETA = 1
    float inv2s2 = 1.0f / (2.0f * sigma * sigma);

    float* __restrict__ src  = out;
    float* __restrict__ tgt  = out + BNK;
    float* __restrict__ attr = out + 2 * BNK;
    float* __restrict__ sloc = out + 3 * BNK;

    const long long base = (long long)row * KNN;
    const float rowf  = (float)row;
    const float boffs = (float)(b * NPTS);
#pragma unroll
    for (int k = 0; k < KNN; k++) {
        src[base + k]  = rowf;
        tgt[base + k]  = boffs + (float)fi[k + 1];
        attr[base + k] = expf(-fd[k + 1] * inv2s2);
    }
    sloc[row] = dk * dk;                       // LAMBDA = 1
}

extern "C" void kernel_launch(void* const* d_in, const int* in_sizes, int n_in,
                              void* d_out, int out_size)
{
    (void)in_sizes; (void)n_in; (void)out_size;
    const float* pc = (const float*)d_in[0];
    float* outp = (float*)d_out;

    const size_t smem1 = (size_t)HALF * sizeof(float4);   // 32 KB
    cudaFuncSetAttribute(knn_partial_kernel,
                         cudaFuncAttributeMaxDynamicSharedMemorySize, (int)smem1);

    knn_partial_kernel<<<BATCH * CHUNKS * NSPLIT, TPB, smem1>>>(pc);
    knn_merge_kernel<<<(BATCH * NPTS) / TPB, TPB>>>(pc, outp);
}

// round 6
// speedup vs baseline: 3.0408x; 3.0408x over previous
#include <cuda_runtime.h>
#include <math.h>

// Problem constants (fixed: point_cloud [8, 4096, 3], K=20)
#define BATCH 8
#define NPTS  4096
#define KNN   20
#define TPB   512
#define WARPS (TPB / 32)          // 16 warps per CTA
#define QPW   4                   // queries per warp (sequential passes)
#define QPC   (WARPS * QPW)       // 64 queries per CTA
#define CPB   (NPTS / QPC)        // 64 CTAs per batch -> grid = 512

__global__ __launch_bounds__(TPB, 3)
void knn_warp_kernel(const float* __restrict__ pc, float* __restrict__ out)
{
    // Whole batch staged as float4 (x, y, z, |p|^2): 64 KB dynamic smem.
    extern __shared__ float4 pts[];

    const int b     = blockIdx.x / CPB;
    const int qbase = (blockIdx.x % CPB) * QPC;
    const float* __restrict__ pcb = pc + (size_t)b * NPTS * 3;

    for (int i = threadIdx.x; i < NPTS; i += TPB) {
        float x = pcb[3 * i + 0];
        float y = pcb[3 * i + 1];
        float z = pcb[3 * i + 2];
        pts[i] = make_float4(x, y, z, fmaf(x, x, fmaf(y, y, z * z)));
    }
    __syncthreads();

    const int warp = threadIdx.x >> 5;
    const int lane = threadIdx.x & 31;
    const float INF = __int_as_float(0x7f800000);

    const long long BNK = (long long)BATCH * NPTS * KNN;
    float* __restrict__ srcA = out;
    float* __restrict__ tgtA = out + BNK;
    float* __restrict__ attA = out + 2 * BNK;
    float* __restrict__ slocA = out + 3 * BNK;

    for (int qq = 0; qq < QPW; qq++) {
        const int qi = qbase + qq * WARPS + warp;      // query index in batch
        const float4 q = pts[qi];
        const float n2qx = -2.0f * q.x, n2qy = -2.0f * q.y, n2qz = -2.0f * q.z;
        const float sqq = q.w;

        // Warp-wide sorted list: lane l holds the (l+1)-th smallest (d2, idx).
        // Exactness is guaranteed for lanes 0..21 (filter thr = lane 21 value):
        // admission uses a (conservative, stale) thr; insertion drops only
        // candidates >= current lane-31 value, which are provably outside the
        // exact top-22.
        float ld = INF;
        int   li = 0;
        float thr = INF;

#pragma unroll 2
        for (int s = 0; s < NPTS / 64; s++) {
            const int j0 = s * 64 + lane;
            const int j1 = j0 + 32;
            float4 p0 = pts[j0];
            float4 p1 = pts[j1];
            float t0 = fmaf(n2qx, p0.x, fmaf(n2qy, p0.y, fmaf(n2qz, p0.z, p0.w)));
            float t1 = fmaf(n2qx, p1.x, fmaf(n2qy, p1.y, fmaf(n2qz, p1.z, p1.w)));
            float d0 = fmaxf(t0 + sqq, 0.0f);
            float d1 = fmaxf(t1 + sqq, 0.0f);

            unsigned m0 = __ballot_sync(0xFFFFFFFFu, d0 < thr);
            unsigned m1 = __ballot_sync(0xFFFFFFFFu, d1 < thr);

            if (m0 | m1) {
                // Drain in ascending candidate-index order (top_k tie stability).
                while (m0) {
                    int srcl = __ffs(m0) - 1; m0 &= m0 - 1;
                    float cd = __shfl_sync(0xFFFFFFFFu, d0, srcl);
                    int   cj = s * 64 + srcl;
                    bool pred = cd < ld;                       // strict: stable ties
                    float ud = __shfl_up_sync(0xFFFFFFFFu, ld, 1);
                    int   ui = __shfl_up_sync(0xFFFFFFFFu, li, 1);
                    unsigned bal = __ballot_sync(0xFFFFFFFFu, pred);
                    int pos = bal ? (__ffs(bal) - 1) : 64;     // 64: drop (>= ld[31])
                    if (lane >= pos) {
                        ld = (lane == pos) ? cd : ud;
                        li = (lane == pos) ? cj : ui;
                    }
                    thr = __shfl_sync(0xFFFFFFFFu, ld, 21);
                }
                while (m1) {
                    int srcl = __ffs(m1) - 1; m1 &= m1 - 1;
                    float cd = __shfl_sync(0xFFFFFFFFu, d1, srcl);
                    int   cj = s * 64 + 32 + srcl;
                    bool pred = cd < ld;
                    float ud = __shfl_up_sync(0xFFFFFFFFu, ld, 1);
                    int   ui = __shfl_up_sync(0xFFFFFFFFu, li, 1);
                    unsigned bal = __ballot_sync(0xFFFFFFFFu, pred);
                    int pos = bal ? (__ffs(bal) - 1) : 64;
                    if (lane >= pos) {
                        ld = (lane == pos) ? cd : ud;
                        li = (lane == pos) ? cj : ui;
                    }
                    thr = __shfl_sync(0xFFFFFFFFu, ld, 21);
                }
            }
        }

        // Lane 0 = self (d2 ~ 0, strict minimum); neighbors = lanes 1..20.
        const int row = b * NPTS + qi;
        float dk2 = __shfl_sync(0xFFFFFFFFu, ld, 20);  // k-th neighbor d2
        float dk = sqrtf(dk2);
        float sigma = dk + 1e-6f;                      // BETA = 1
        float inv2s2 = 1.0f / (2.0f * sigma * sigma);

        const long long base = (long long)row * KNN;
        if (lane >= 1 && lane <= KNN) {
            int k = lane - 1;
            srcA[base + k] = (float)row;
            tgtA[base + k] = (float)(b * NPTS + li);
            attA[base + k] = expf(-ld * inv2s2);
        }
        if (lane == 0) slocA[row] = dk * dk;           // LAMBDA = 1
    }
}

extern "C" void kernel_launch(void* const* d_in, const int* in_sizes, int n_in,
                              void* d_out, int out_size)
{
    (void)in_sizes; (void)n_in; (void)out_size;
    const float* pc = (const float*)d_in[0];
    float* outp = (float*)d_out;

    const size_t smem = (size_t)NPTS * sizeof(float4);   // 64 KB
    cudaFuncSetAttribute(knn_warp_kernel,
                         cudaFuncAttributeMaxDynamicSharedMemorySize, (int)smem);
    knn_warp_kernel<<<BATCH * CPB, TPB, smem>>>(pc, outp);
}

// round 7
// speedup vs baseline: 3.8256x; 1.2581x over previous
#include <cuda_runtime.h>
#include <math.h>

// Problem constants (fixed: point_cloud [8, 4096, 3], K=20)
#define BATCH 8
#define NPTS  4096
#define KNN   20
#define TPB   512
#define WARPS (TPB / 32)          // 16 warps per CTA
#define CPB   55                  // CTAs per batch -> grid = 440 (one balanced wave @3/SM)
#define FULLM 0xFFFFFFFFu

__global__ __launch_bounds__(TPB, 3)
void knn_warp_kernel(const float* __restrict__ pc, float* __restrict__ out)
{
    // Whole batch staged as float4 (x, y, z, |p|^2): 64 KB dynamic smem.
    extern __shared__ float4 pts[];

    const int b   = blockIdx.x / CPB;
    const int cta = blockIdx.x % CPB;
    const float* __restrict__ pcb = pc + (size_t)b * NPTS * 3;

    for (int i = threadIdx.x; i < NPTS; i += TPB) {
        float x = pcb[3 * i + 0];
        float y = pcb[3 * i + 1];
        float z = pcb[3 * i + 2];
        pts[i] = make_float4(x, y, z, fmaf(x, x, fmaf(y, y, z * z)));
    }
    __syncthreads();

    const int warp = threadIdx.x >> 5;
    const int lane = threadIdx.x & 31;
    const float INF = __int_as_float(0x7f800000);

    // Uneven query split across the 55 CTAs of this batch (74-75 each).
    const int qstart = (NPTS * cta) / CPB;
    const int qend   = (NPTS * (cta + 1)) / CPB;

    const long long BNK = (long long)BATCH * NPTS * KNN;
    float* __restrict__ srcA = out;
    float* __restrict__ tgtA = out + BNK;
    float* __restrict__ attA = out + 2 * BNK;
    float* __restrict__ slocA = out + 3 * BNK;

    for (int qi = qstart + warp; qi < qend; qi += WARPS) {
        const float4 q = pts[qi];
        const float n2qx = -2.0f * q.x, n2qy = -2.0f * q.y, n2qz = -2.0f * q.z;
        const float sqq = q.w;

        // Warp-wide sorted list: lane l holds the (l+1)-th smallest (d2, idx).
        // Admission threshold (lane 21 snapshot) is conservative/stale; any
        // candidate >= current lane-31 value produces an all-false pred and is
        // dropped -- provably outside the exact top-22, so lanes 0..21 stay exact.
        float ld = INF;
        int   li = 0;
        float thr = INF;

#pragma unroll 2
        for (int s = 0; s < NPTS / 64; s++) {
            const int j0 = s * 64 + lane;
            float4 p0 = pts[j0];
            float4 p1 = pts[j0 + 32];
            float t0 = fmaf(n2qx, p0.x, fmaf(n2qy, p0.y, fmaf(n2qz, p0.z, p0.w)));
            float t1 = fmaf(n2qx, p1.x, fmaf(n2qy, p1.y, fmaf(n2qz, p1.z, p1.w)));
            float d0 = fmaxf(t0 + sqq, 0.0f);
            float d1 = fmaxf(t1 + sqq, 0.0f);

            unsigned m0 = __ballot_sync(FULLM, d0 < thr);
            unsigned m1 = __ballot_sync(FULLM, d1 < thr);

            if (m0 | m1) {
                // Drain in ascending candidate-index order (top_k tie stability).
                // pred is a suffix mask over the sorted list, so the insertion
                // point is the unique lane with pred && !pred_prev.
                while (m0) {
                    int srcl = __ffs(m0) - 1; m0 &= m0 - 1;
                    float cd = __shfl_sync(FULLM, d0, srcl);
                    int   cj = s * 64 + srcl;
                    float ud = __shfl_up_sync(FULLM, ld, 1);
                    int   ui = __shfl_up_sync(FULLM, li, 1);
                    bool pred  = cd < ld;                     // strict: stable ties
                    bool predp = (lane > 0) && (cd < ud);
                    if (pred) {
                        ld = predp ? ud : cd;
                        li = predp ? ui : cj;
                    }
                }
                while (m1) {
                    int srcl = __ffs(m1) - 1; m1 &= m1 - 1;
                    float cd = __shfl_sync(FULLM, d1, srcl);
                    int   cj = s * 64 + 32 + srcl;
                    float ud = __shfl_up_sync(FULLM, ld, 1);
                    int   ui = __shfl_up_sync(FULLM, li, 1);
                    bool pred  = cd < ld;
                    bool predp = (lane > 0) && (cd < ud);
                    if (pred) {
                        ld = predp ? ud : cd;
                        li = predp ? ui : cj;
                    }
                }
                thr = __shfl_sync(FULLM, ld, 21);   // refresh once per batch
            }
        }

        // Lane 0 = self (d2 ~ 0, strict minimum); neighbors = lanes 1..20.
        const int row = b * NPTS + qi;
        float dk2 = __shfl_sync(FULLM, ld, 20);     // k-th neighbor d2
        float dk = sqrtf(dk2);
        float sigma = dk + 1e-6f;                   // BETA = 1
        float inv2s2 = 1.0f / (2.0f * sigma * sigma);

        const long long base = (long long)row * KNN;
        if (lane >= 1 && lane <= KNN) {
            int k = lane - 1;
            srcA[base + k] = (float)row;
            tgtA[base + k] = (float)(b * NPTS + li);
            attA[base + k] = expf(-ld * inv2s2);
        }
        if (lane == 0) slocA[row] = dk * dk;        // LAMBDA = 1
    }
}

extern "C" void kernel_launch(void* const* d_in, const int* in_sizes, int n_in,
                              void* d_out, int out_size)
{
    (void)in_sizes; (void)n_in; (void)out_size;
    const float* pc = (const float*)d_in[0];
    float* outp = (float*)d_out;

    const size_t smem = (size_t)NPTS * sizeof(float4);   // 64 KB
    cudaFuncSetAttribute(knn_warp_kernel,
                         cudaFuncAttributeMaxDynamicSharedMemorySize, (int)smem);
    knn_warp_kernel<<<BATCH * CPB, TPB, smem>>>(pc, outp);
}

// round 8
// speedup vs baseline: 4.4909x; 1.1739x over previous
#include <cuda_runtime.h>
#include <math.h>

// Problem constants (fixed: point_cloud [8, 4096, 3], K=20)
#define BATCH 8
#define NPTS  4096
#define KNN   20
#define TPB   512
#define WARPS (TPB / 32)          // 16 warps per CTA
#define CPB   55                  // CTAs per batch -> grid = 440 (one balanced wave @3/SM)
#define FULLM 0xFFFFFFFFu

__global__ __launch_bounds__(TPB, 3)
void knn_warp_kernel(const float* __restrict__ pc, float* __restrict__ out)
{
    // Whole batch staged as float4 (x, y, z, |p|^2): 64 KB dynamic smem.
    extern __shared__ float4 pts[];
    __shared__ int qctr;

    const int b   = blockIdx.x / CPB;
    const int cta = blockIdx.x % CPB;
    const float* __restrict__ pcb = pc + (size_t)b * NPTS * 3;

    if (threadIdx.x == 0) qctr = 0;
    for (int i = threadIdx.x; i < NPTS; i += TPB) {
        float x = pcb[3 * i + 0];
        float y = pcb[3 * i + 1];
        float z = pcb[3 * i + 2];
        pts[i] = make_float4(x, y, z, fmaf(x, x, fmaf(y, y, z * z)));
    }
    __syncthreads();

    const int lane = threadIdx.x & 31;

    // Query range for this CTA (74-75 queries), dynamically stolen by warps.
    const int qstart = (NPTS * cta) / CPB;
    const int qcount = (NPTS * (cta + 1)) / CPB - qstart;

    const long long BNK = (long long)BATCH * NPTS * KNN;
    float* __restrict__ srcA = out;
    float* __restrict__ tgtA = out + BNK;
    float* __restrict__ attA = out + 2 * BNK;
    float* __restrict__ slocA = out + 3 * BNK;

    for (;;) {
        int t;
        if (lane == 0) t = atomicAdd(&qctr, 1);
        t = __shfl_sync(FULLM, t, 0);
        if (t >= qcount) break;
        const int qi = qstart + t;

        const float4 q = pts[qi];
        const float n2qx = -2.0f * q.x, n2qy = -2.0f * q.y, n2qz = -2.0f * q.z;
        const float sqq = q.w;

        // ---- seed: exact sort of the first 32 candidates ----------------
        // Lane-sorted list: lane l holds the (l+1)-th smallest (d2, idx),
        // lexicographic (d2, idx) -- identical semantics to stable insertion.
        float ld;
        int   li = lane;
        {
            float4 p = pts[lane];
            float tt = fmaf(n2qx, p.x, fmaf(n2qy, p.y, fmaf(n2qz, p.z, p.w)));
            ld = fmaxf(tt + sqq, 0.0f);
        }
#pragma unroll
        for (int k = 2; k <= 32; k <<= 1) {
#pragma unroll
            for (int j = k >> 1; j > 0; j >>= 1) {
                float od = __shfl_xor_sync(FULLM, ld, j);
                int   oi = __shfl_xor_sync(FULLM, li, j);
                bool up     = (lane & k) == 0;       // ascending block
                bool iLower = (lane & j) == 0;       // lower index of the pair
                bool oless  = (od < ld) || ((od == ld) && (oi < li));
                bool take   = (iLower == up) ? oless : !oless;
                if (take) { ld = od; li = oi; }
            }
        }
        float thr = __shfl_sync(FULLM, ld, 21);

        // ---- half batch: candidates 32..63 -------------------------------
        {
            float4 p0 = pts[32 + lane];
            float t0 = fmaf(n2qx, p0.x, fmaf(n2qy, p0.y, fmaf(n2qz, p0.z, p0.w)));
            float d0 = fmaxf(t0 + sqq, 0.0f);
            unsigned m0 = __ballot_sync(FULLM, d0 < thr);
            while (m0) {
                int srcl = __ffs(m0) - 1; m0 &= m0 - 1;
                float cd = __shfl_sync(FULLM, d0, srcl);
                int   cj = 32 + srcl;
                float ud = __shfl_up_sync(FULLM, ld, 1);
                int   ui = __shfl_up_sync(FULLM, li, 1);
                bool pred  = cd < ld;                 // strict: stable ties
                bool predp = (lane > 0) && (cd < ud);
                if (pred) {
                    ld = predp ? ud : cd;
                    li = predp ? ui : cj;
                }
            }
            thr = __shfl_sync(FULLM, ld, 21);
        }

        // ---- full batches: candidates 64..4095 ---------------------------
        // Admission thr (lane-21 snapshot) is conservative/stale; a candidate
        // >= current lane-31 value yields all-false pred and is dropped --
        // provably outside the exact top-22, so lanes 0..21 stay exact.
#pragma unroll 2
        for (int s = 0; s < (NPTS - 64) / 64; s++) {
            const int j0 = 64 + s * 64 + lane;
            float4 p0 = pts[j0];
            float4 p1 = pts[j0 + 32];
            float t0 = fmaf(n2qx, p0.x, fmaf(n2qy, p0.y, fmaf(n2qz, p0.z, p0.w)));
            float t1 = fmaf(n2qx, p1.x, fmaf(n2qy, p1.y, fmaf(n2qz, p1.z, p1.w)));
            float d0 = fmaxf(t0 + sqq, 0.0f);
            float d1 = fmaxf(t1 + sqq, 0.0f);

            unsigned m0 = __ballot_sync(FULLM, d0 < thr);
            unsigned m1 = __ballot_sync(FULLM, d1 < thr);

            if (m0 | m1) {
                // Drain ascending candidate index (top_k tie stability).
                while (m0) {
                    int srcl = __ffs(m0) - 1; m0 &= m0 - 1;
                    float cd = __shfl_sync(FULLM, d0, srcl);
                    int   cj = j0 - lane + srcl;
                    float ud = __shfl_up_sync(FULLM, ld, 1);
                    int   ui = __shfl_up_sync(FULLM, li, 1);
                    bool pred  = cd < ld;
                    bool predp = (lane > 0) && (cd < ud);
                    if (pred) {
                        ld = predp ? ud : cd;
                        li = predp ? ui : cj;
                    }
                }
                while (m1) {
                    int srcl = __ffs(m1) - 1; m1 &= m1 - 1;
                    float cd = __shfl_sync(FULLM, d1, srcl);
                    int   cj = j0 - lane + 32 + srcl;
                    float ud = __shfl_up_sync(FULLM, ld, 1);
                    int   ui = __shfl_up_sync(FULLM, li, 1);
                    bool pred  = cd < ld;
                    bool predp = (lane > 0) && (cd < ud);
                    if (pred) {
                        ld = predp ? ud : cd;
                        li = predp ? ui : cj;
                    }
                }
                thr = __shfl_sync(FULLM, ld, 21);     // refresh once per batch
            }
        }

        // Lane 0 = self (d2 ~ 0, strict minimum); neighbors = lanes 1..20.
        const int row = b * NPTS + qi;
        float dk2 = __shfl_sync(FULLM, ld, 20);       // k-th neighbor d2
        float dk = sqrtf(dk2);
        float sigma = dk + 1e-6f;                     // BETA = 1
        float inv2s2 = 1.0f / (2.0f * sigma * sigma);

        const long long base = (long long)row * KNN;
        if (lane >= 1 && lane <= KNN) {
            int k = lane - 1;
            srcA[base + k] = (float)row;
            tgtA[base + k] = (float)(b * NPTS + li);
            attA[base + k] = expf(-ld * inv2s2);
        }
        if (lane == 0) slocA[row] = dk * dk;          // LAMBDA = 1
    }
}

extern "C" void kernel_launch(void* const* d_in, const int* in_sizes, int n_in,
                              void* d_out, int out_size)
{
    (void)in_sizes; (void)n_in; (void)out_size;
    const float* pc = (const float*)d_in[0];
    float* outp = (float*)d_out;

    const size_t smem = (size_t)NPTS * sizeof(float4);   // 64 KB
    cudaFuncSetAttribute(knn_warp_kernel,
                         cudaFuncAttributeMaxDynamicSharedMemorySize, (int)smem);
    knn_warp_kernel<<<BATCH * CPB, TPB, smem>>>(pc, outp);
}